// round 14
// baseline (speedup 1.0000x reference)
#include <cuda_runtime.h>
#include <cuda_fp16.h>
#include <stdint.h>
#include <math.h>

// Mixtral sparse MoE, GB300 sm_103a. T=2048, H=1024, E=8, F=2816, top-2.
// fp16 mma.sync m16n8k16, fp32 accum. 512 thr/CTA, 64 accum regs, 1 sync/iter.
constexpr int T = 2048, H = 1024, E = 8, F = 2816;
constexpr int AMAX = 2 * T, APAD = AMAX + 256;

__device__ __half g_xh[(size_t)APAD * H];     // gathered tokens, fp16
__device__ __half g_acth[(size_t)APAD * F];   // SwiGLU activations, fp16
__device__ float  g_y[(size_t)AMAX * H];      // per-slot down proj
__device__ int   g_cnt[E], g_off[E], g_cur[E];
__device__ int   g_top_e[T * 2];
__device__ float g_top_w[T * 2];
__device__ int   g_assign_tok[AMAX];
__device__ float g_assign_w[AMAX];
__device__ int   g_tok2slot[T * 2];
__device__ float g_logits_dummy[T * E];

// ---------------- helpers ----------------
__device__ __forceinline__ uint32_t h2(float a, float b) {   // pack 2 fp16 (RN)
    uint32_t r;
    asm("{.reg .b16 lo,hi; cvt.rn.f16.f32 lo,%1; cvt.rn.f16.f32 hi,%2; mov.b32 %0,{lo,hi};}"
        : "=r"(r) : "f"(a), "f"(b));
    return r;
}
__device__ __forceinline__ void mma_f16(float* c, const uint32_t* a, const uint32_t* b) {
    asm volatile(
        "mma.sync.aligned.m16n8k16.row.col.f32.f16.f16.f32 "
        "{%0,%1,%2,%3}, {%4,%5,%6,%7}, {%8,%9}, {%0,%1,%2,%3};\n"
        : "+f"(c[0]), "+f"(c[1]), "+f"(c[2]), "+f"(c[3])
        : "r"(a[0]), "r"(a[1]), "r"(a[2]), "r"(a[3]), "r"(b[0]), "r"(b[1]));
}
__device__ __forceinline__ void ldsm4(uint32_t& r0, uint32_t& r1, uint32_t& r2, uint32_t& r3,
                                      uint32_t a) {
    asm volatile("ldmatrix.sync.aligned.m8n8.x4.shared.b16 {%0,%1,%2,%3}, [%4];"
                 : "=r"(r0), "=r"(r1), "=r"(r2), "=r"(r3) : "r"(a));
}
__device__ __forceinline__ void ldsm4t(uint32_t& r0, uint32_t& r1, uint32_t& r2, uint32_t& r3,
                                       uint32_t a) {
    asm volatile("ldmatrix.sync.aligned.m8n8.x4.trans.shared.b16 {%0,%1,%2,%3}, [%4];"
                 : "=r"(r0), "=r"(r1), "=r"(r2), "=r"(r3) : "r"(a));
}
__device__ __forceinline__ uint32_t smem_u32(const void* p) {
    uint32_t a;
    asm("{ .reg .u64 t; cvta.to.shared.u64 t, %1; cvt.u32.u64 %0, t; }" : "=r"(a) : "l"(p));
    return a;
}
__device__ __forceinline__ void cpa16(uint32_t dst, const void* src) {
    asm volatile("cp.async.cg.shared.global [%0], [%1], 16;" :: "r"(dst), "l"(src));
}
__device__ __forceinline__ void cp_commit() { asm volatile("cp.async.commit_group;"); }
template <int N> __device__ __forceinline__ void cp_wait() {
    asm volatile("cp.async.wait_group %0;" :: "n"(N));
}
__device__ __forceinline__ void sts64(uint32_t a, uint32_t x, uint32_t y) {
    asm volatile("st.shared.v2.b32 [%0], {%1,%2};" :: "r"(a), "r"(x), "r"(y) : "memory");
}

// ---------------- small kernels ----------------
__global__ __launch_bounds__(256) void router_kernel(
    const float* __restrict__ x, const float* __restrict__ gw, float* __restrict__ logits_out) {
    __shared__ float sgw[E * H];
    int tid = threadIdx.x;
    for (int i = tid; i < E * H; i += 256) sgw[i] = gw[i];
    __syncthreads();
    int warp = tid >> 5, lane = tid & 31;
    int t = blockIdx.x * 8 + warp;
    float xr[32];
    const float* xp = x + (size_t)t * H;
#pragma unroll
    for (int i = 0; i < 32; i++) xr[i] = xp[i * 32 + lane];
    float l[E];
#pragma unroll
    for (int e = 0; e < E; e++) {
        float acc = 0.f;
        const float* g = sgw + e * H;
#pragma unroll
        for (int i = 0; i < 32; i++) acc += xr[i] * g[i * 32 + lane];
#pragma unroll
        for (int o = 16; o > 0; o >>= 1) acc += __shfl_xor_sync(0xffffffffu, acc, o);
        l[e] = acc;
    }
    if (lane == 0) {
#pragma unroll
        for (int e = 0; e < E; e++) logits_out[(size_t)t * E + e] = l[e];
        int e0 = 0; float b0 = l[0];
#pragma unroll
        for (int e = 1; e < E; e++) if (l[e] > b0) { b0 = l[e]; e0 = e; }
        int e1 = (e0 == 0) ? 1 : 0; float b1 = l[e1];
#pragma unroll
        for (int e = 0; e < E; e++) if (e != e0 && l[e] > b1) { b1 = l[e]; e1 = e; }
        float p = expf(b1 - b0), inv = 1.f / (1.f + p);
        g_top_e[2 * t] = e0;     g_top_w[2 * t] = inv;
        g_top_e[2 * t + 1] = e1; g_top_w[2 * t + 1] = p * inv;
        atomicAdd(&g_cnt[e0], 1);
        atomicAdd(&g_cnt[e1], 1);
    }
}

__global__ void scan_kernel() {
    int off = 0;
    for (int e = 0; e < E; e++) { g_off[e] = off; g_cur[e] = off; off += g_cnt[e]; }
}

// fused slot assignment + token gather (block per assignment)
__global__ __launch_bounds__(256) void assign_gather_kernel(const float* __restrict__ x) {
    __shared__ int s_slot, s_tok;
    int bid = blockIdx.x;                 // 0..AMAX-1  (= 2*t + k)
    if (threadIdx.x == 0) {
        int t = bid >> 1;
        int e = g_top_e[bid];
        int slot = atomicAdd(&g_cur[e], 1);
        g_assign_tok[slot] = t;
        g_assign_w[slot] = g_top_w[bid];
        g_tok2slot[bid] = slot;
        s_slot = slot; s_tok = t;
    }
    __syncthreads();
    int slot = s_slot, tok = s_tok;
    float4 f = ((const float4*)(x + (size_t)tok * H))[threadIdx.x];
    ((uint2*)(g_xh + (size_t)slot * H))[threadIdx.x] =
        make_uint2(h2(f.x, f.y), h2(f.z, f.w));
}

// ---------------------------------------------------------------------------
// GEMMs: 512 thr (16 warps, 4x4 grid, warp tile 32x32), CTA tile 128x128,
// K-stage 32, 3-buffer ring, ONE barrier per K-iter:
//   [cp_wait<1>; sync] -> ldgB(i+2) -> compute(i) -> stsB(i+2) -> cpA(i+2)
// A stride 40 halves, B stride 136 halves: conflict-free ldmatrix.
// ---------------------------------------------------------------------------
constexpr int A_ST_B = 128 * 80;       // 10240 B per A stage
constexpr int B_ST_B = 32 * 272;       // 8704 B per B stage
constexpr int G1_SMEM = 3 * (A_ST_B + 2 * B_ST_B);   // 82944
constexpr int G2_SMEM = 3 * (A_ST_B + B_ST_B);       // 56832

// GEMM1: act = rw * silu(X@w1) * (X@w3)
__global__ void __launch_bounds__(512, 1) gemm1_kernel(
    const float* __restrict__ w1, const float* __restrict__ w3) {
    const int e = blockIdx.z, mt = blockIdx.y;
    const int cnt = g_cnt[e];
    if (mt * 128 >= cnt) return;
    const int off = g_off[e];
    const int n0 = blockIdx.x * 128;

    extern __shared__ uint8_t smb[];
    const uint32_t sb = smem_u32(smb);
    __shared__ float swt[128];

    const int tid = threadIdx.x;
    if (tid < 128) {
        int r = mt * 128 + tid;
        swt[tid] = (r < cnt) ? g_assign_w[off + r] : 0.f;
    }

    const __half* Ah = g_xh + (size_t)(off + mt * 128) * H;
    const float* w1p = w1 + (size_t)e * H * F + n0;
    const float* w3p = w3 + (size_t)e * H * F + n0;

    uint4 br1[2], br3[2];
    auto ldgB = [&](int k0) {
#pragma unroll
        for (int v = 0; v < 2; v++) {
            int idx = tid + v * 512;
            int row = idx >> 5, nn = (idx & 31) * 4;
            size_t g = (size_t)(k0 + row) * F + nn;
            br1[v] = *(const uint4*)(w1p + g);
            br3[v] = *(const uint4*)(w3p + g);
        }
    };
    auto stsB = [&](int s) {
        const uint32_t b1b = sb + 3 * A_ST_B + s * B_ST_B;
        const uint32_t b3b = sb + 3 * A_ST_B + (3 + s) * B_ST_B;
#pragma unroll
        for (int v = 0; v < 2; v++) {
            int idx = tid + v * 512;
            int row = idx >> 5, nn = (idx & 31) * 4;
            float4 f1 = *(float4*)&br1[v];
            sts64(b1b + row * 272 + nn * 2, h2(f1.x, f1.y), h2(f1.z, f1.w));
            float4 f3 = *(float4*)&br3[v];
            sts64(b3b + row * 272 + nn * 2, h2(f3.x, f3.y), h2(f3.z, f3.w));
        }
    };
    auto cpA = [&](int s, int k0) {
        int row = tid >> 2, c = tid & 3;
        cpa16(sb + s * A_ST_B + row * 80 + c * 16, Ah + (size_t)row * H + k0 + c * 8);
        cp_commit();
    };

    const int lane = tid & 31, warp = tid >> 5;
    const int wm = warp >> 2, wn = warp & 3;     // 4x4 grid; warp tile 32x32
    const int lr = lane >> 2, lc = lane & 3;
    const int l15 = lane & 15, l16 = lane >> 4;

    float accG[2][4][4], accU[2][4][4];
#pragma unroll
    for (int i = 0; i < 2; i++)
#pragma unroll
        for (int j = 0; j < 4; j++)
#pragma unroll
            for (int c = 0; c < 4; c++) { accG[i][j][c] = 0.f; accU[i][j][c] = 0.f; }

    // prologue: stages 0,1 staged
    ldgB(0);  stsB(0); cpA(0, 0);
    ldgB(32); stsB(1); cpA(1, 32);

    const int NK = H / 32;  // 32
    for (int i = 0; i < NK; i++) {
        cp_wait<1>();
        __syncthreads();                       // A(i) visible; iter i-1 reads done
        if (i + 2 < NK) ldgB((i + 2) * 32);    // LDG in flight under compute

        int s = i % 3;
        const uint32_t Asm = sb + s * A_ST_B;
        const uint32_t B1sm = sb + 3 * A_ST_B + s * B_ST_B;
        const uint32_t B3sm = sb + 3 * A_ST_B + (3 + s) * B_ST_B;
#pragma unroll
        for (int kk = 0; kk < 2; kk++) {
            uint32_t a[2][4];
#pragma unroll
            for (int mi = 0; mi < 2; mi++)
                ldsm4(a[mi][0], a[mi][1], a[mi][2], a[mi][3],
                      Asm + (wm * 32 + mi * 16 + l15) * 80 + (kk * 16 + l16 * 8) * 2);
            uint32_t b1[2][4], b3[2][4];
#pragma unroll
            for (int np = 0; np < 2; np++) {
                uint32_t ba = (kk * 16 + l15) * 272 + (wn * 32 + np * 16 + l16 * 8) * 2;
                ldsm4t(b1[np][0], b1[np][1], b1[np][2], b1[np][3], B1sm + ba);
                ldsm4t(b3[np][0], b3[np][1], b3[np][2], b3[np][3], B3sm + ba);
            }
#pragma unroll
            for (int ni = 0; ni < 4; ni++) {
                int np = ni >> 1, pr = (ni & 1) * 2;
                uint32_t bb1[2] = { b1[np][pr], b1[np][pr + 1] };
                uint32_t bb3[2] = { b3[np][pr], b3[np][pr + 1] };
#pragma unroll
                for (int mi = 0; mi < 2; mi++) {
                    mma_f16(accG[mi][ni], a[mi], bb1);
                    mma_f16(accU[mi][ni], a[mi], bb3);
                }
            }
        }

        if (i + 2 < NK) {
            stsB((i + 2) % 3);                 // cell (i+2)%3: reads ended iter i-1
            cpA((i + 2) % 3, (i + 2) * 32);
        } else {
            cp_commit();                       // keep group count in step
        }
    }

    // epilogue: act = rw * u * silu(g), stored fp16
#pragma unroll
    for (int mi = 0; mi < 2; mi++)
#pragma unroll
        for (int hf = 0; hf < 2; hf++) {
            int row = wm * 32 + mi * 16 + lr + hf * 8;
            int grow = mt * 128 + row;
            if (grow < cnt) {
                float w = swt[row];
                __half* dst = g_acth + (size_t)(off + grow) * F + n0;
#pragma unroll
                for (int ni = 0; ni < 4; ni++) {
                    int col = wn * 32 + ni * 8 + lc * 2;
                    float gg = accG[mi][ni][hf * 2], uu = accU[mi][ni][hf * 2];
                    float a0 = w * uu * (gg / (1.f + expf(-gg)));
                    gg = accG[mi][ni][hf * 2 + 1]; uu = accU[mi][ni][hf * 2 + 1];
                    float a1 = w * uu * (gg / (1.f + expf(-gg)));
                    *(uint32_t*)(dst + col) = h2(a0, a1);
                }
            }
        }
}

// GEMM2: y = act @ w2[e]; K=2816
__global__ void __launch_bounds__(512, 1) gemm2_kernel(const float* __restrict__ w2) {
    const int e = blockIdx.z, mt = blockIdx.y;
    const int cnt = g_cnt[e];
    if (mt * 128 >= cnt) return;
    const int off = g_off[e];
    const int n0 = blockIdx.x * 128;

    extern __shared__ uint8_t smb[];
    const uint32_t sb = smem_u32(smb);
    const int tid = threadIdx.x;

    const __half* Ah = g_acth + (size_t)(off + mt * 128) * F;
    const float* Wp = w2 + (size_t)e * F * H + n0;

    uint4 br[2];
    auto ldgB = [&](int k0) {
#pragma unroll
        for (int v = 0; v < 2; v++) {
            int idx = tid + v * 512;
            int row = idx >> 5, nn = (idx & 31) * 4;
            br[v] = *(const uint4*)(Wp + (size_t)(k0 + row) * H + nn);
        }
    };
    auto stsB = [&](int s) {
        const uint32_t bb = sb + 3 * A_ST_B + s * B_ST_B;
#pragma unroll
        for (int v = 0; v < 2; v++) {
            int idx = tid + v * 512;
            int row = idx >> 5, nn = (idx & 31) * 4;
            float4 f = *(float4*)&br[v];
            sts64(bb + row * 272 + nn * 2, h2(f.x, f.y), h2(f.z, f.w));
        }
    };
    auto cpA = [&](int s, int k0) {
        int row = tid >> 2, c = tid & 3;
        cpa16(sb + s * A_ST_B + row * 80 + c * 16, Ah + (size_t)row * F + k0 + c * 8);
        cp_commit();
    };

    const int lane = tid & 31, warp = tid >> 5;
    const int wm = warp >> 2, wn = warp & 3;
    const int lr = lane >> 2, lc = lane & 3;
    const int l15 = lane & 15, l16 = lane >> 4;

    float acc[2][4][4];
#pragma unroll
    for (int i = 0; i < 2; i++)
#pragma unroll
        for (int j = 0; j < 4; j++)
#pragma unroll
            for (int c = 0; c < 4; c++) acc[i][j][c] = 0.f;

    ldgB(0);  stsB(0); cpA(0, 0);
    ldgB(32); stsB(1); cpA(1, 32);

    const int NK = F / 32;  // 88
    for (int i = 0; i < NK; i++) {
        cp_wait<1>();
        __syncthreads();
        if (i + 2 < NK) ldgB((i + 2) * 32);

        int s = i % 3;
        const uint32_t Asm = sb + s * A_ST_B;
        const uint32_t Bsm = sb + 3 * A_ST_B + s * B_ST_B;
#pragma unroll
        for (int kk = 0; kk < 2; kk++) {
            uint32_t a[2][4];
#pragma unroll
            for (int mi = 0; mi < 2; mi++)
                ldsm4(a[mi][0], a[mi][1], a[mi][2], a[mi][3],
                      Asm + (wm * 32 + mi * 16 + l15) * 80 + (kk * 16 + l16 * 8) * 2);
            uint32_t b[2][4];
#pragma unroll
            for (int np = 0; np < 2; np++) {
                uint32_t ba = (kk * 16 + l15) * 272 + (wn * 32 + np * 16 + l16 * 8) * 2;
                ldsm4t(b[np][0], b[np][1], b[np][2], b[np][3], Bsm + ba);
            }
#pragma unroll
            for (int ni = 0; ni < 4; ni++) {
                int np = ni >> 1, pr = (ni & 1) * 2;
                uint32_t bb[2] = { b[np][pr], b[np][pr + 1] };
#pragma unroll
                for (int mi = 0; mi < 2; mi++) mma_f16(acc[mi][ni], a[mi], bb);
            }
        }

        if (i + 2 < NK) {
            stsB((i + 2) % 3);
            cpA((i + 2) % 3, (i + 2) * 32);
        } else {
            cp_commit();
        }
    }

#pragma unroll
    for (int mi = 0; mi < 2; mi++)
#pragma unroll
        for (int hf = 0; hf < 2; hf++) {
            int row = wm * 32 + mi * 16 + lr + hf * 8;
            int grow = mt * 128 + row;
            if (grow < cnt) {
                float* dst = g_y + (size_t)(off + grow) * H + n0;
#pragma unroll
                for (int ni = 0; ni < 4; ni++) {
                    int col = wn * 32 + ni * 8 + lc * 2;
                    *(float2*)(dst + col) =
                        make_float2(acc[mi][ni][hf * 2], acc[mi][ni][hf * 2 + 1]);
                }
            }
        }
}

// ---------------- combine (+ re-zero counts for the next graph replay) ------
__global__ void combine_kernel(float* __restrict__ out) {
    if (blockIdx.x == 0 && threadIdx.x < E) g_cnt[threadIdx.x] = 0;
    int t = blockIdx.x;
    int s0 = g_tok2slot[2 * t], s1 = g_tok2slot[2 * t + 1];
    float4 a = ((const float4*)(g_y + (size_t)s0 * H))[threadIdx.x];
    float4 b = ((const float4*)(g_y + (size_t)s1 * H))[threadIdx.x];
    ((float4*)(out + (size_t)t * H))[threadIdx.x] =
        make_float4(a.x + b.x, a.y + b.y, a.z + b.z, a.w + b.w);
}

// ---------------- launch ----------------
extern "C" void kernel_launch(void* const* d_in, const int* in_sizes, int n_in,
                              void* d_out, int out_size) {
    const float* x  = (const float*)d_in[0];
    const float* gw = (const float*)d_in[1];
    const float* w1 = (const float*)d_in[2];
    const float* w3 = (const float*)d_in[3];
    const float* w2 = (const float*)d_in[4];
    float* out = (float*)d_out;

    float* logits;
    if (out_size >= T * H + T * E) logits = out + (size_t)T * H;
    else cudaGetSymbolAddress((void**)&logits, g_logits_dummy);

    cudaFuncSetAttribute(gemm1_kernel, cudaFuncAttributeMaxDynamicSharedMemorySize, G1_SMEM);
    cudaFuncSetAttribute(gemm2_kernel, cudaFuncAttributeMaxDynamicSharedMemorySize, G2_SMEM);

    // g_cnt zero on first run (static init); combine_kernel re-zeroes each run.
    router_kernel<<<T / 8, 256>>>(x, gw, logits);
    scan_kernel<<<1, 1>>>();
    assign_gather_kernel<<<AMAX, 256>>>(x);
    gemm1_kernel<<<dim3(F / 128, 16, E), 512, G1_SMEM>>>(w1, w3);
    gemm2_kernel<<<dim3(H / 128, 16, E), 512, G2_SMEM>>>(w2);
    combine_kernel<<<T, 256>>>(out);
}

// round 15
// speedup vs baseline: 1.0185x; 1.0185x over previous
#include <cuda_runtime.h>
#include <cuda_fp16.h>
#include <stdint.h>
#include <math.h>

// Mixtral sparse MoE, GB300 sm_103a. T=2048, H=1024, E=8, F=2816, top-2.
// fp16 mma.sync m16n8k16, fp32 accum. 512 thr/CTA, 64 accum regs, 1 sync/iter.
constexpr int T = 2048, H = 1024, E = 8, F = 2816;
constexpr int AMAX = 2 * T, APAD = AMAX + 256;

__device__ __half g_xh[(size_t)APAD * H];     // gathered tokens, fp16
__device__ __half g_acth[(size_t)APAD * F];   // SwiGLU activations, fp16
__device__ float  g_y[(size_t)AMAX * H];      // per-slot down proj
__device__ int   g_cnt[E], g_off[E], g_cur[E];
__device__ int   g_top_e[T * 2];
__device__ float g_top_w[T * 2];
__device__ int   g_assign_tok[AMAX];
__device__ float g_assign_w[AMAX];
__device__ int   g_tok2slot[T * 2];
__device__ float g_logits_dummy[T * E];

// ---------------- helpers ----------------
__device__ __forceinline__ uint32_t h2(float a, float b) {   // pack 2 fp16 (RN)
    uint32_t r;
    asm("{.reg .b16 lo,hi; cvt.rn.f16.f32 lo,%1; cvt.rn.f16.f32 hi,%2; mov.b32 %0,{lo,hi};}"
        : "=r"(r) : "f"(a), "f"(b));
    return r;
}
__device__ __forceinline__ void mma_f16(float* c, const uint32_t* a, const uint32_t* b) {
    asm volatile(
        "mma.sync.aligned.m16n8k16.row.col.f32.f16.f16.f32 "
        "{%0,%1,%2,%3}, {%4,%5,%6,%7}, {%8,%9}, {%0,%1,%2,%3};\n"
        : "+f"(c[0]), "+f"(c[1]), "+f"(c[2]), "+f"(c[3])
        : "r"(a[0]), "r"(a[1]), "r"(a[2]), "r"(a[3]), "r"(b[0]), "r"(b[1]));
}
__device__ __forceinline__ void ldsm4(uint32_t& r0, uint32_t& r1, uint32_t& r2, uint32_t& r3,
                                      uint32_t a) {
    asm volatile("ldmatrix.sync.aligned.m8n8.x4.shared.b16 {%0,%1,%2,%3}, [%4];"
                 : "=r"(r0), "=r"(r1), "=r"(r2), "=r"(r3) : "r"(a));
}
__device__ __forceinline__ void ldsm4t(uint32_t& r0, uint32_t& r1, uint32_t& r2, uint32_t& r3,
                                       uint32_t a) {
    asm volatile("ldmatrix.sync.aligned.m8n8.x4.trans.shared.b16 {%0,%1,%2,%3}, [%4];"
                 : "=r"(r0), "=r"(r1), "=r"(r2), "=r"(r3) : "r"(a));
}
__device__ __forceinline__ uint32_t smem_u32(const void* p) {
    uint32_t a;
    asm("{ .reg .u64 t; cvta.to.shared.u64 t, %1; cvt.u32.u64 %0, t; }" : "=r"(a) : "l"(p));
    return a;
}
__device__ __forceinline__ void cpa16(uint32_t dst, const void* src) {
    asm volatile("cp.async.cg.shared.global [%0], [%1], 16;" :: "r"(dst), "l"(src));
}
__device__ __forceinline__ void cp_commit() { asm volatile("cp.async.commit_group;"); }
template <int N> __device__ __forceinline__ void cp_wait() {
    asm volatile("cp.async.wait_group %0;" :: "n"(N));
}
__device__ __forceinline__ void sts64(uint32_t a, uint32_t x, uint32_t y) {
    asm volatile("st.shared.v2.b32 [%0], {%1,%2};" :: "r"(a), "r"(x), "r"(y) : "memory");
}

// ---------------- small kernels ----------------
__global__ __launch_bounds__(256) void router_kernel(
    const float* __restrict__ x, const float* __restrict__ gw, float* __restrict__ logits_out) {
    __shared__ float sgw[E * H];
    int tid = threadIdx.x;
    for (int i = tid; i < E * H; i += 256) sgw[i] = gw[i];
    __syncthreads();
    int warp = tid >> 5, lane = tid & 31;
    int t = blockIdx.x * 8 + warp;
    float xr[32];
    const float* xp = x + (size_t)t * H;
#pragma unroll
    for (int i = 0; i < 32; i++) xr[i] = xp[i * 32 + lane];
    float l[E];
#pragma unroll
    for (int e = 0; e < E; e++) {
        float acc = 0.f;
        const float* g = sgw + e * H;
#pragma unroll
        for (int i = 0; i < 32; i++) acc += xr[i] * g[i * 32 + lane];
#pragma unroll
        for (int o = 16; o > 0; o >>= 1) acc += __shfl_xor_sync(0xffffffffu, acc, o);
        l[e] = acc;
    }
    if (lane == 0) {
#pragma unroll
        for (int e = 0; e < E; e++) logits_out[(size_t)t * E + e] = l[e];
        int e0 = 0; float b0 = l[0];
#pragma unroll
        for (int e = 1; e < E; e++) if (l[e] > b0) { b0 = l[e]; e0 = e; }
        int e1 = (e0 == 0) ? 1 : 0; float b1 = l[e1];
#pragma unroll
        for (int e = 0; e < E; e++) if (e != e0 && l[e] > b1) { b1 = l[e]; e1 = e; }
        float p = expf(b1 - b0), inv = 1.f / (1.f + p);
        g_top_e[2 * t] = e0;     g_top_w[2 * t] = inv;
        g_top_e[2 * t + 1] = e1; g_top_w[2 * t + 1] = p * inv;
        atomicAdd(&g_cnt[e0], 1);
        atomicAdd(&g_cnt[e1], 1);
    }
}

__global__ void scan_kernel() {
    int off = 0;
    for (int e = 0; e < E; e++) { g_off[e] = off; g_cur[e] = off; off += g_cnt[e]; }
}

// fused slot assignment + token gather (block per assignment)
__global__ __launch_bounds__(256) void assign_gather_kernel(const float* __restrict__ x) {
    __shared__ int s_slot, s_tok;
    int bid = blockIdx.x;                 // 0..AMAX-1  (= 2*t + k)
    if (threadIdx.x == 0) {
        int t = bid >> 1;
        int e = g_top_e[bid];
        int slot = atomicAdd(&g_cur[e], 1);
        g_assign_tok[slot] = t;
        g_assign_w[slot] = g_top_w[bid];
        g_tok2slot[bid] = slot;
        s_slot = slot; s_tok = t;
    }
    __syncthreads();
    int slot = s_slot, tok = s_tok;
    float4 f = ((const float4*)(x + (size_t)tok * H))[threadIdx.x];
    ((uint2*)(g_xh + (size_t)slot * H))[threadIdx.x] =
        make_uint2(h2(f.x, f.y), h2(f.z, f.w));
}

// ---------------------------------------------------------------------------
// GEMMs: 512 thr (16 warps, 4x4 grid, warp tile 32x32), CTA tile 128x128,
// K-stage 32, 3-buffer ring, ONE barrier per K-iter:
//   [cp_wait<1>; sync] -> ldgB(i+2) -> compute(i) -> stsB(i+2) -> cpA(i+2)
// A stride 40 halves, B stride 136 halves: conflict-free ldmatrix.
// ---------------------------------------------------------------------------
constexpr int A_ST_B = 128 * 80;       // 10240 B per A stage
constexpr int B_ST_B = 32 * 272;       // 8704 B per B stage
constexpr int G1_SMEM = 3 * (A_ST_B + 2 * B_ST_B);   // 82944
constexpr int G2_SMEM = 3 * (A_ST_B + B_ST_B);       // 56832

// GEMM1: act = rw * silu(X@w1) * (X@w3)
__global__ void __launch_bounds__(512, 1) gemm1_kernel(
    const float* __restrict__ w1, const float* __restrict__ w3) {
    const int e = blockIdx.z, mt = blockIdx.y;
    const int cnt = g_cnt[e];
    if (mt * 128 >= cnt) return;
    const int off = g_off[e];
    const int n0 = blockIdx.x * 128;

    extern __shared__ uint8_t smb[];
    const uint32_t sb = smem_u32(smb);
    __shared__ float swt[128];

    const int tid = threadIdx.x;
    if (tid < 128) {
        int r = mt * 128 + tid;
        swt[tid] = (r < cnt) ? g_assign_w[off + r] : 0.f;
    }

    const __half* Ah = g_xh + (size_t)(off + mt * 128) * H;
    const float* w1p = w1 + (size_t)e * H * F + n0;
    const float* w3p = w3 + (size_t)e * H * F + n0;

    uint4 br1[2], br3[2];
    auto ldgB = [&](int k0) {
#pragma unroll
        for (int v = 0; v < 2; v++) {
            int idx = tid + v * 512;
            int row = idx >> 5, nn = (idx & 31) * 4;
            size_t g = (size_t)(k0 + row) * F + nn;
            br1[v] = *(const uint4*)(w1p + g);
            br3[v] = *(const uint4*)(w3p + g);
        }
    };
    auto stsB = [&](int s) {
        const uint32_t b1b = sb + 3 * A_ST_B + s * B_ST_B;
        const uint32_t b3b = sb + 3 * A_ST_B + (3 + s) * B_ST_B;
#pragma unroll
        for (int v = 0; v < 2; v++) {
            int idx = tid + v * 512;
            int row = idx >> 5, nn = (idx & 31) * 4;
            float4 f1 = *(float4*)&br1[v];
            sts64(b1b + row * 272 + nn * 2, h2(f1.x, f1.y), h2(f1.z, f1.w));
            float4 f3 = *(float4*)&br3[v];
            sts64(b3b + row * 272 + nn * 2, h2(f3.x, f3.y), h2(f3.z, f3.w));
        }
    };
    auto cpA = [&](int s, int k0) {
        int row = tid >> 2, c = tid & 3;
        cpa16(sb + s * A_ST_B + row * 80 + c * 16, Ah + (size_t)row * H + k0 + c * 8);
        cp_commit();
    };

    const int lane = tid & 31, warp = tid >> 5;
    const int wm = warp >> 2, wn = warp & 3;     // 4x4 grid; warp tile 32x32
    const int lr = lane >> 2, lc = lane & 3;
    const int l15 = lane & 15, l16 = lane >> 4;

    float accG[2][4][4], accU[2][4][4];
#pragma unroll
    for (int i = 0; i < 2; i++)
#pragma unroll
        for (int j = 0; j < 4; j++)
#pragma unroll
            for (int c = 0; c < 4; c++) { accG[i][j][c] = 0.f; accU[i][j][c] = 0.f; }

    // prologue: stages 0,1 staged
    ldgB(0);  stsB(0); cpA(0, 0);
    ldgB(32); stsB(1); cpA(1, 32);

    const int NK = H / 32;  // 32
    for (int i = 0; i < NK; i++) {
        cp_wait<1>();
        __syncthreads();                       // A(i) visible; iter i-1 reads done
        if (i + 2 < NK) ldgB((i + 2) * 32);    // LDG in flight under compute

        int s = i % 3;
        const uint32_t Asm = sb + s * A_ST_B;
        const uint32_t B1sm = sb + 3 * A_ST_B + s * B_ST_B;
        const uint32_t B3sm = sb + 3 * A_ST_B + (3 + s) * B_ST_B;
#pragma unroll
        for (int kk = 0; kk < 2; kk++) {
            uint32_t a[2][4];
#pragma unroll
            for (int mi = 0; mi < 2; mi++)
                ldsm4(a[mi][0], a[mi][1], a[mi][2], a[mi][3],
                      Asm + (wm * 32 + mi * 16 + l15) * 80 + (kk * 16 + l16 * 8) * 2);
            uint32_t b1[2][4], b3[2][4];
#pragma unroll
            for (int np = 0; np < 2; np++) {
                uint32_t ba = (kk * 16 + l15) * 272 + (wn * 32 + np * 16 + l16 * 8) * 2;
                ldsm4t(b1[np][0], b1[np][1], b1[np][2], b1[np][3], B1sm + ba);
                ldsm4t(b3[np][0], b3[np][1], b3[np][2], b3[np][3], B3sm + ba);
            }
#pragma unroll
            for (int ni = 0; ni < 4; ni++) {
                int np = ni >> 1, pr = (ni & 1) * 2;
                uint32_t bb1[2] = { b1[np][pr], b1[np][pr + 1] };
                uint32_t bb3[2] = { b3[np][pr], b3[np][pr + 1] };
#pragma unroll
                for (int mi = 0; mi < 2; mi++) {
                    mma_f16(accG[mi][ni], a[mi], bb1);
                    mma_f16(accU[mi][ni], a[mi], bb3);
                }
            }
        }

        if (i + 2 < NK) {
            stsB((i + 2) % 3);                 // cell (i+2)%3: reads ended iter i-1
            cpA((i + 2) % 3, (i + 2) * 32);
        } else {
            cp_commit();                       // keep group count in step
        }
    }

    // epilogue: act = rw * u * silu(g), stored fp16
#pragma unroll
    for (int mi = 0; mi < 2; mi++)
#pragma unroll
        for (int hf = 0; hf < 2; hf++) {
            int row = wm * 32 + mi * 16 + lr + hf * 8;
            int grow = mt * 128 + row;
            if (grow < cnt) {
                float w = swt[row];
                __half* dst = g_acth + (size_t)(off + grow) * F + n0;
#pragma unroll
                for (int ni = 0; ni < 4; ni++) {
                    int col = wn * 32 + ni * 8 + lc * 2;
                    float gg = accG[mi][ni][hf * 2], uu = accU[mi][ni][hf * 2];
                    float a0 = w * uu * (gg / (1.f + expf(-gg)));
                    gg = accG[mi][ni][hf * 2 + 1]; uu = accU[mi][ni][hf * 2 + 1];
                    float a1 = w * uu * (gg / (1.f + expf(-gg)));
                    *(uint32_t*)(dst + col) = h2(a0, a1);
                }
            }
        }
}

// GEMM2: y = act @ w2[e]; K=2816
__global__ void __launch_bounds__(512, 1) gemm2_kernel(const float* __restrict__ w2) {
    const int e = blockIdx.z, mt = blockIdx.y;
    const int cnt = g_cnt[e];
    if (mt * 128 >= cnt) return;
    const int off = g_off[e];
    const int n0 = blockIdx.x * 128;

    extern __shared__ uint8_t smb[];
    const uint32_t sb = smem_u32(smb);
    const int tid = threadIdx.x;

    const __half* Ah = g_acth + (size_t)(off + mt * 128) * F;
    const float* Wp = w2 + (size_t)e * F * H + n0;

    uint4 br[2];
    auto ldgB = [&](int k0) {
#pragma unroll
        for (int v = 0; v < 2; v++) {
            int idx = tid + v * 512;
            int row = idx >> 5, nn = (idx & 31) * 4;
            br[v] = *(const uint4*)(Wp + (size_t)(k0 + row) * H + nn);
        }
    };
    auto stsB = [&](int s) {
        const uint32_t bb = sb + 3 * A_ST_B + s * B_ST_B;
#pragma unroll
        for (int v = 0; v < 2; v++) {
            int idx = tid + v * 512;
            int row = idx >> 5, nn = (idx & 31) * 4;
            float4 f = *(float4*)&br[v];
            sts64(bb + row * 272 + nn * 2, h2(f.x, f.y), h2(f.z, f.w));
        }
    };
    auto cpA = [&](int s, int k0) {
        int row = tid >> 2, c = tid & 3;
        cpa16(sb + s * A_ST_B + row * 80 + c * 16, Ah + (size_t)row * F + k0 + c * 8);
        cp_commit();
    };

    const int lane = tid & 31, warp = tid >> 5;
    const int wm = warp >> 2, wn = warp & 3;
    const int lr = lane >> 2, lc = lane & 3;
    const int l15 = lane & 15, l16 = lane >> 4;

    float acc[2][4][4];
#pragma unroll
    for (int i = 0; i < 2; i++)
#pragma unroll
        for (int j = 0; j < 4; j++)
#pragma unroll
            for (int c = 0; c < 4; c++) acc[i][j][c] = 0.f;

    ldgB(0);  stsB(0); cpA(0, 0);
    ldgB(32); stsB(1); cpA(1, 32);

    const int NK = F / 32;  // 88
    for (int i = 0; i < NK; i++) {
        cp_wait<1>();
        __syncthreads();
        if (i + 2 < NK) ldgB((i + 2) * 32);

        int s = i % 3;
        const uint32_t Asm = sb + s * A_ST_B;
        const uint32_t Bsm = sb + 3 * A_ST_B + s * B_ST_B;
#pragma unroll
        for (int kk = 0; kk < 2; kk++) {
            uint32_t a[2][4];
#pragma unroll
            for (int mi = 0; mi < 2; mi++)
                ldsm4(a[mi][0], a[mi][1], a[mi][2], a[mi][3],
                      Asm + (wm * 32 + mi * 16 + l15) * 80 + (kk * 16 + l16 * 8) * 2);
            uint32_t b[2][4];
#pragma unroll
            for (int np = 0; np < 2; np++) {
                uint32_t ba = (kk * 16 + l15) * 272 + (wn * 32 + np * 16 + l16 * 8) * 2;
                ldsm4t(b[np][0], b[np][1], b[np][2], b[np][3], Bsm + ba);
            }
#pragma unroll
            for (int ni = 0; ni < 4; ni++) {
                int np = ni >> 1, pr = (ni & 1) * 2;
                uint32_t bb[2] = { b[np][pr], b[np][pr + 1] };
#pragma unroll
                for (int mi = 0; mi < 2; mi++) mma_f16(acc[mi][ni], a[mi], bb);
            }
        }

        if (i + 2 < NK) {
            stsB((i + 2) % 3);
            cpA((i + 2) % 3, (i + 2) * 32);
        } else {
            cp_commit();
        }
    }

#pragma unroll
    for (int mi = 0; mi < 2; mi++)
#pragma unroll
        for (int hf = 0; hf < 2; hf++) {
            int row = wm * 32 + mi * 16 + lr + hf * 8;
            int grow = mt * 128 + row;
            if (grow < cnt) {
                float* dst = g_y + (size_t)(off + grow) * H + n0;
#pragma unroll
                for (int ni = 0; ni < 4; ni++) {
                    int col = wn * 32 + ni * 8 + lc * 2;
                    *(float2*)(dst + col) =
                        make_float2(acc[mi][ni][hf * 2], acc[mi][ni][hf * 2 + 1]);
                }
            }
        }
}

// ---------------- combine (+ re-zero counts for the next graph replay) ------
__global__ void combine_kernel(float* __restrict__ out) {
    if (blockIdx.x == 0 && threadIdx.x < E) g_cnt[threadIdx.x] = 0;
    int t = blockIdx.x;
    int s0 = g_tok2slot[2 * t], s1 = g_tok2slot[2 * t + 1];
    float4 a = ((const float4*)(g_y + (size_t)s0 * H))[threadIdx.x];
    float4 b = ((const float4*)(g_y + (size_t)s1 * H))[threadIdx.x];
    ((float4*)(out + (size_t)t * H))[threadIdx.x] =
        make_float4(a.x + b.x, a.y + b.y, a.z + b.z, a.w + b.w);
}

// ---------------- launch ----------------
extern "C" void kernel_launch(void* const* d_in, const int* in_sizes, int n_in,
                              void* d_out, int out_size) {
    const float* x  = (const float*)d_in[0];
    const float* gw = (const float*)d_in[1];
    const float* w1 = (const float*)d_in[2];
    const float* w3 = (const float*)d_in[3];
    const float* w2 = (const float*)d_in[4];
    float* out = (float*)d_out;

    float* logits;
    if (out_size >= T * H + T * E) logits = out + (size_t)T * H;
    else cudaGetSymbolAddress((void**)&logits, g_logits_dummy);

    cudaFuncSetAttribute(gemm1_kernel, cudaFuncAttributeMaxDynamicSharedMemorySize, G1_SMEM);
    cudaFuncSetAttribute(gemm2_kernel, cudaFuncAttributeMaxDynamicSharedMemorySize, G2_SMEM);

    // g_cnt zero on first run (static init); combine_kernel re-zeroes each run.
    router_kernel<<<T / 8, 256>>>(x, gw, logits);
    scan_kernel<<<1, 1>>>();
    assign_gather_kernel<<<AMAX, 256>>>(x);
    gemm1_kernel<<<dim3(F / 128, 16, E), 512, G1_SMEM>>>(w1, w3);
    gemm2_kernel<<<dim3(H / 128, 16, E), 512, G2_SMEM>>>(w2);
    combine_kernel<<<T, 256>>>(out);
}